// round 10
// baseline (speedup 1.0000x reference)
#include <cuda_runtime.h>
#include <math.h>
#include <stdint.h>

// Problem constants
#define QS    512
#define BATCH 8
#define CDIM  1024
#define NHEAD 16
#define HCDIM 64
#define MMEM  1536
#define NTOK  (QS * BATCH)   // 4096

// Scratch (device globals: allocation-guard safe)
__device__ float g_q[NTOK * CDIM];
__device__ float g_k[NTOK * CDIM];
__device__ float g_v[NTOK * CDIM];
__device__ float g_x[NTOK * CDIM];

__device__ __forceinline__ uint32_t f2tf32(float f) {
    uint32_t u;
    asm("cvt.rna.tf32.f32 %0, %1;" : "=r"(u) : "f"(f));
    return u;
}

__device__ __forceinline__ void mma_tf32(float c[4],
    uint32_t a0, uint32_t a1, uint32_t a2, uint32_t a3,
    uint32_t b0, uint32_t b1)
{
    asm volatile(
        "mma.sync.aligned.m16n8k8.row.col.f32.tf32.tf32.f32 "
        "{%0,%1,%2,%3}, {%4,%5,%6,%7}, {%8,%9}, {%0,%1,%2,%3};"
        : "+f"(c[0]), "+f"(c[1]), "+f"(c[2]), "+f"(c[3])
        : "r"(a0), "r"(a1), "r"(a2), "r"(a3), "r"(b0), "r"(b1));
}

__device__ __forceinline__ void cp16(uint32_t dst, const void* src, int sz) {
    asm volatile("cp.async.cg.shared.global [%0], [%1], 16, %2;"
                 :: "r"(dst), "l"(src), "r"(sz));
}
__device__ __forceinline__ void cp_commit() {
    asm volatile("cp.async.commit_group;");
}
__device__ __forceinline__ void cp_wait0() {
    asm volatile("cp.async.wait_group 0;");
}
__device__ __forceinline__ void cp_wait1() {
    asm volatile("cp.async.wait_group 1;");
}

// ---------------------------------------------------------------------------
// TF32 tensor-core GEMM: out[n][o] = sum_k A[n][k] * W[o][k] + bias[o]
// Block tile 128x128, k-chunk 32, 8 warps (2x4), warp tile 64x32.
// Register double-buffered global loads (keeps cvt.rna precision).
// Measured ~4.0 cyc/mma == HMMA tf32 path ceiling.
// ---------------------------------------------------------------------------
__global__ __launch_bounds__(256) void gemm_tf32_nt_bias(
    const float* __restrict__ A, const float* __restrict__ W,
    const float* __restrict__ bias, float* __restrict__ out)
{
    __shared__ uint32_t As[128 * 36];
    __shared__ uint32_t Ws[128 * 36];

    const int tid  = threadIdx.x;
    const int lane = tid & 31;
    const int warp = tid >> 5;
    const int g    = lane >> 2;
    const int tig  = lane & 3;

    const int wm = (warp >> 2) * 64;
    const int wn = (warp & 3) * 32;

    const int n0 = blockIdx.y << 7;
    const int o0 = blockIdx.x << 7;

    const int lrow = tid >> 3;
    const int lcol = (tid & 7) << 2;

    float c[4][4][4];
    #pragma unroll
    for (int mi = 0; mi < 4; mi++)
        #pragma unroll
        for (int ni = 0; ni < 4; ni++)
            #pragma unroll
            for (int r = 0; r < 4; r++) c[mi][ni][r] = 0.0f;

    float4 ra[4], rw[4];
    #pragma unroll
    for (int p = 0; p < 4; p++) {
        int r = lrow + (p << 5);
        ra[p] = *(const float4*)(A + (size_t)(n0 + r) * CDIM + lcol);
        rw[p] = *(const float4*)(W + (size_t)(o0 + r) * CDIM + lcol);
    }

    for (int k0 = 0; k0 < CDIM; k0 += 32) {
        #pragma unroll
        for (int p = 0; p < 4; p++) {
            int r = lrow + (p << 5);
            As[r * 36 + lcol + 0] = f2tf32(ra[p].x);
            As[r * 36 + lcol + 1] = f2tf32(ra[p].y);
            As[r * 36 + lcol + 2] = f2tf32(ra[p].z);
            As[r * 36 + lcol + 3] = f2tf32(ra[p].w);
            Ws[r * 36 + lcol + 0] = f2tf32(rw[p].x);
            Ws[r * 36 + lcol + 1] = f2tf32(rw[p].y);
            Ws[r * 36 + lcol + 2] = f2tf32(rw[p].z);
            Ws[r * 36 + lcol + 3] = f2tf32(rw[p].w);
        }
        __syncthreads();

        if (k0 + 32 < CDIM) {
            #pragma unroll
            for (int p = 0; p < 4; p++) {
                int r = lrow + (p << 5);
                ra[p] = *(const float4*)(A + (size_t)(n0 + r) * CDIM + k0 + 32 + lcol);
                rw[p] = *(const float4*)(W + (size_t)(o0 + r) * CDIM + k0 + 32 + lcol);
            }
        }

        #pragma unroll
        for (int ks = 0; ks < 4; ks++) {
            const int kk = ks << 3;
            uint32_t a[4][4], b[4][2];
            #pragma unroll
            for (int mi = 0; mi < 4; mi++) {
                const uint32_t* ap = As + (wm + (mi << 4) + g) * 36 + kk + tig;
                a[mi][0] = ap[0];
                a[mi][1] = ap[8 * 36];
                a[mi][2] = ap[4];
                a[mi][3] = ap[8 * 36 + 4];
            }
            #pragma unroll
            for (int ni = 0; ni < 4; ni++) {
                const uint32_t* bp = Ws + (wn + (ni << 3) + g) * 36 + kk + tig;
                b[ni][0] = bp[0];
                b[ni][1] = bp[4];
            }
            #pragma unroll
            for (int mi = 0; mi < 4; mi++)
                #pragma unroll
                for (int ni = 0; ni < 4; ni++)
                    mma_tf32(c[mi][ni], a[mi][0], a[mi][1], a[mi][2], a[mi][3],
                             b[ni][0], b[ni][1]);
        }
        __syncthreads();
    }

    #pragma unroll
    for (int mi = 0; mi < 4; mi++) {
        int row = n0 + wm + (mi << 4) + g;
        #pragma unroll
        for (int ni = 0; ni < 4; ni++) {
            int col = o0 + wn + (ni << 3) + (tig << 1);
            float b0 = bias[col], b1 = bias[col + 1];
            float2 v0 = make_float2(c[mi][ni][0] + b0, c[mi][ni][1] + b1);
            float2 v1 = make_float2(c[mi][ni][2] + b0, c[mi][ni][3] + b1);
            *(float2*)(out + (size_t)row * CDIM + col) = v0;
            *(float2*)(out + (size_t)(row + 8) * CDIM + col) = v1;
        }
    }
}

// ---------------------------------------------------------------------------
// TF32 tensor-core flash attention, 2-stage cp.async pipelined KV gather.
// Grid: (QS/64, BATCH*NHEAD). Block: 128 threads (4 warps), 64q x 64k tiles.
// K stored [kj][d] stride 68, V stored [t][c] stride 72 -- conflict-free.
// After cp.async arrival each thread rna-converts ITS OWN copied words in
// place (restores rna precision: rel_err ~6.1e-4 vs 9.7e-4 truncated).
// Grid y remapped b = y&7 so each wave mixes batches (Teff balance).
// Tiles fully inside memory (t0+64 <= L) skip all masking.
// ---------------------------------------------------------------------------
#define KSTR 68
#define VSTR 72
#define KV_WORDS (64 * KSTR + 64 * VSTR)   // one stage: 8960 words

__global__ __launch_bounds__(128) void attn_tc_kernel(
    const float* __restrict__ qg, const float* __restrict__ kg,
    const float* __restrict__ vg, const float* __restrict__ memkv,
    const int* __restrict__ memlen, const int* __restrict__ padv,
    const unsigned char* __restrict__ mask, float* __restrict__ xout)
{
    extern __shared__ uint32_t smu[];   // 2 * KV_WORDS = 17920 words = 71680 B
    const uint32_t smem_base = (uint32_t)__cvta_generic_to_shared(smu);

    const int tid  = threadIdx.x;
    const int lane = tid & 31;
    const int warp = tid >> 5;       // 0..3
    const int g    = lane >> 2;      // 0..7
    const int tig  = lane & 3;       // 0..3

    const int s0 = blockIdx.x << 6;
    const int b  = blockIdx.y & 7;    // interleave batches across waves
    const int h  = blockIdx.y >> 3;
    const int L  = memlen[b];
    const int P  = padv[b];
    const int Teff = L + P;
    const int qrow0 = warp * 16 + g;

    // ---- Stage Q through smem (buffer 0), then into register fragments ----
    {
        float* Qst = (float*)smu;   // [qi][d] stride 68
        for (int i = tid; i < 1024; i += 128) {
            int qi = i >> 4;
            int dc = (i & 15) << 2;
            float4 qv = *(const float4*)(qg + ((size_t)(s0 + qi) * BATCH + b) * CDIM + h * HCDIM + dc);
            *(float4*)(Qst + qi * KSTR + dc) = qv;
        }
    }
    __syncthreads();

    uint32_t qf[8][4];
    {
        const float* q0 = (const float*)smu + qrow0 * KSTR;
        const float* q8 = q0 + 8 * KSTR;
        #pragma unroll
        for (int ks = 0; ks < 8; ks++) {
            const int kk = ks << 3;
            qf[ks][0] = f2tf32(q0[kk + tig] * 0.125f);
            qf[ks][1] = f2tf32(q8[kk + tig] * 0.125f);
            qf[ks][2] = f2tf32(q0[kk + tig + 4] * 0.125f);
            qf[ks][3] = f2tf32(q8[kk + tig + 4] * 0.125f);
        }
    }
    __syncthreads();  // Q staging consumed before prefetch overwrites buffer 0

    float oacc[8][4];
    #pragma unroll
    for (int ni = 0; ni < 8; ni++)
        #pragma unroll
        for (int r = 0; r < 4; r++) oacc[ni][r] = 0.0f;
    float mrow[2] = { -INFINITY, -INFINITY };
    float lrow[2] = { 0.0f, 0.0f };

    const int ntile = (Teff + 63) >> 6;

    // ---- KV gather into stage buffer via cp.async ----
    auto gather = [&](int kt) {
        const int t0 = kt << 6;
        const uint32_t kbase = smem_base + (uint32_t)((kt & 1) * KV_WORDS) * 4u;
        const uint32_t vbase = kbase + 64 * KSTR * 4u;
        for (int i = tid; i < 1024; i += 128) {
            int kj = i >> 4;
            int dc = (i & 15) << 2;
            int t = t0 + kj;
            const float* srcK = kg;
            const float* srcV = vg;
            int sz = 0;
            if (t < L) {
                const float* bp = memkv + (((size_t)t * BATCH + b) * NHEAD + h) * (2 * HCDIM);
                srcK = bp + dc;
                srcV = bp + HCDIM + dc;
                sz = 16;
            } else if (t < Teff) {
                int j = t - L;
                srcK = kg + ((size_t)j * BATCH + b) * CDIM + h * HCDIM + dc;
                srcV = vg + ((size_t)j * BATCH + b) * CDIM + h * HCDIM + dc;
                sz = 16;
            }
            cp16(kbase + (uint32_t)(kj * KSTR + dc) * 4u, srcK, sz);
            cp16(vbase + (uint32_t)(kj * VSTR + dc) * 4u, srcV, sz);
        }
        cp_commit();
    };

    if (ntile > 0) gather(0);

    for (int kt = 0; kt < ntile; kt++) {
        const int t0 = kt << 6;
        if (kt + 1 < ntile) { gather(kt + 1); cp_wait1(); }
        else                { cp_wait0(); }

        // In-place rna conversion of OWN cp'd words (same (kj,dc) mapping as
        // gather -> own data, no barrier needed between wait and convert).
        {
            uint32_t* Kw = smu + (kt & 1) * KV_WORDS;
            uint32_t* Vw = Kw + 64 * KSTR;
            for (int i = tid; i < 1024; i += 128) {
                int kj = i >> 4;
                int dc = (i & 15) << 2;
                uint32_t* kp = Kw + kj * KSTR + dc;
                float4 kv = *(const float4*)kp;
                kp[0] = f2tf32(kv.x); kp[1] = f2tf32(kv.y);
                kp[2] = f2tf32(kv.z); kp[3] = f2tf32(kv.w);
                uint32_t* vp = Vw + kj * VSTR + dc;
                float4 vv = *(const float4*)vp;
                vp[0] = f2tf32(vv.x); vp[1] = f2tf32(vv.y);
                vp[2] = f2tf32(vv.z); vp[3] = f2tf32(vv.w);
            }
        }
        __syncthreads();

        const uint32_t* Kb = smu + (kt & 1) * KV_WORDS;
        const uint32_t* Vb = Kb + 64 * KSTR;

        // S = Q K^T
        float sv[8][4];
        #pragma unroll
        for (int ni = 0; ni < 8; ni++)
            #pragma unroll
            for (int r = 0; r < 4; r++) sv[ni][r] = 0.0f;

        #pragma unroll
        for (int ks = 0; ks < 8; ks++) {
            const int kk = ks << 3;
            #pragma unroll
            for (int ni = 0; ni < 8; ni++) {
                const uint32_t* bp = Kb + ((ni << 3) + g) * KSTR + kk + tig;
                mma_tf32(sv[ni], qf[ks][0], qf[ks][1], qf[ks][2], qf[ks][3],
                         bp[0], bp[4]);
            }
        }

        // Masking -- skipped entirely for tiles fully inside memory region
        if (t0 + 64 > L) {
            #pragma unroll
            for (int ni = 0; ni < 8; ni++) {
                #pragma unroll
                for (int cc = 0; cc < 2; cc++) {
                    int t = t0 + (ni << 3) + (tig << 1) + cc;
                    if (t >= Teff) {
                        sv[ni][cc] = -INFINITY;
                        sv[ni][2 + cc] = -INFINITY;
                    } else if (t >= L) {
                        int jn = t - L;
                        int r0 = s0 + qrow0;
                        if (mask[((size_t)r0 * QS + jn) * BATCH + b]) sv[ni][cc] = -INFINITY;
                        if (mask[((size_t)(r0 + 8) * QS + jn) * BATCH + b]) sv[ni][2 + cc] = -INFINITY;
                    }
                }
            }
        }

        // Online softmax per row-half (row spread over 4 tig lanes)
        #pragma unroll
        for (int half = 0; half < 2; half++) {
            const int o0i = half << 1;
            float rm = -INFINITY;
            #pragma unroll
            for (int ni = 0; ni < 8; ni++)
                rm = fmaxf(rm, fmaxf(sv[ni][o0i], sv[ni][o0i + 1]));
            rm = fmaxf(rm, __shfl_xor_sync(0xffffffffu, rm, 1));
            rm = fmaxf(rm, __shfl_xor_sync(0xffffffffu, rm, 2));
            float mn = fmaxf(mrow[half], rm);
            float factor = (mn == -INFINITY) ? 1.0f : __expf(mrow[half] - mn);
            float rs = 0.0f;
            #pragma unroll
            for (int ni = 0; ni < 8; ni++) {
                #pragma unroll
                for (int cc = 0; cc < 2; cc++) {
                    float p = (mn == -INFINITY) ? 0.0f : __expf(sv[ni][o0i + cc] - mn);
                    sv[ni][o0i + cc] = p;
                    rs += p;
                }
            }
            rs += __shfl_xor_sync(0xffffffffu, rs, 1);
            rs += __shfl_xor_sync(0xffffffffu, rs, 2);
            lrow[half] = lrow[half] * factor + rs;
            mrow[half] = mn;
            #pragma unroll
            for (int ni = 0; ni < 8; ni++) {
                oacc[ni][o0i] *= factor;
                oacc[ni][o0i + 1] *= factor;
            }
        }

        // O += P V. P C-frag -> A-frag via intra-group shuffles:
        // col c of block ks lives at lane (g*4 + (c>>1)), slot (c&1).
        const int srcA = (lane & ~3) + (tig >> 1);
        const int srcB = srcA + 2;
        const int sel  = tig & 1;
        #pragma unroll
        for (int ks = 0; ks < 8; ks++) {
            float s0a = __shfl_sync(0xffffffffu, sv[ks][0], srcA);
            float s1a = __shfl_sync(0xffffffffu, sv[ks][1], srcA);
            float s2a = __shfl_sync(0xffffffffu, sv[ks][2], srcA);
            float s3a = __shfl_sync(0xffffffffu, sv[ks][3], srcA);
            float s0b = __shfl_sync(0xffffffffu, sv[ks][0], srcB);
            float s1b = __shfl_sync(0xffffffffu, sv[ks][1], srcB);
            float s2b = __shfl_sync(0xffffffffu, sv[ks][2], srcB);
            float s3b = __shfl_sync(0xffffffffu, sv[ks][3], srcB);
            uint32_t pa0 = f2tf32(sel ? s1a : s0a);   // P[g][8ks+tig]
            uint32_t pa1 = f2tf32(sel ? s3a : s2a);   // P[g+8][8ks+tig]
            uint32_t pa2 = f2tf32(sel ? s1b : s0b);   // P[g][8ks+tig+4]
            uint32_t pa3 = f2tf32(sel ? s3b : s2b);   // P[g+8][8ks+tig+4]

            const int kk = ks << 3;
            #pragma unroll
            for (int ni = 0; ni < 8; ni++) {
                const uint32_t* bp = Vb + (kk + tig) * VSTR + (ni << 3) + g;
                mma_tf32(oacc[ni], pa0, pa1, pa2, pa3, bp[0], bp[4 * VSTR]);
            }
        }
        __syncthreads();  // done reading this stage before it becomes prefetch target
    }

    // Normalize and write x[s][b][c] (all-masked rows -> 0)
    #pragma unroll
    for (int half = 0; half < 2; half++) {
        float inv = (lrow[half] > 0.0f) ? 1.0f / lrow[half] : 0.0f;
        int row = s0 + qrow0 + (half << 3);
        float* orow = xout + ((size_t)row * BATCH + b) * CDIM + h * HCDIM;
        #pragma unroll
        for (int ni = 0; ni < 8; ni++) {
            int col = (ni << 3) + (tig << 1);
            float2 v = make_float2(oacc[ni][(half << 1)] * inv,
                                   oacc[ni][(half << 1) + 1] * inv);
            *(float2*)(orow + col) = v;
        }
    }
}

// ---------------------------------------------------------------------------
// Launch
// ---------------------------------------------------------------------------
extern "C" void kernel_launch(void* const* d_in, const int* in_sizes, int n_in,
                              void* d_out, int out_size)
{
    const float*         xq     = (const float*)d_in[0];
    const int*           pad    = (const int*)d_in[1];
    const unsigned char* mask   = (const unsigned char*)d_in[2];
    const int*           memlen = (const int*)d_in[3];
    const float*         memkv  = (const float*)d_in[4];
    const float* Wq = (const float*)d_in[5];  const float* bq = (const float*)d_in[6];
    const float* Wk = (const float*)d_in[7];  const float* bk = (const float*)d_in[8];
    const float* Wv = (const float*)d_in[9];  const float* bv = (const float*)d_in[10];
    const float* Wo = (const float*)d_in[11]; const float* bo = (const float*)d_in[12];
    float* out = (float*)d_out;

    float *gq, *gk, *gv, *gx;
    cudaGetSymbolAddress((void**)&gq, g_q);
    cudaGetSymbolAddress((void**)&gk, g_k);
    cudaGetSymbolAddress((void**)&gv, g_v);
    cudaGetSymbolAddress((void**)&gx, g_x);

    dim3 gg(CDIM / 128, NTOK / 128);  // (8, 32)
    gemm_tf32_nt_bias<<<gg, 256>>>(xq, Wq, bq, gq);
    gemm_tf32_nt_bias<<<gg, 256>>>(xq, Wk, bk, gk);
    gemm_tf32_nt_bias<<<gg, 256>>>(xq, Wv, bv, gv);

    const int smem_bytes = 2 * KV_WORDS * (int)sizeof(uint32_t);  // 71680
    cudaFuncSetAttribute(attn_tc_kernel, cudaFuncAttributeMaxDynamicSharedMemorySize, smem_bytes);
    attn_tc_kernel<<<dim3(QS / 64, BATCH * NHEAD), 128, smem_bytes>>>(
        gq, gk, gv, memkv, memlen, pad, mask, gx);

    gemm_tf32_nt_bias<<<gg, 256>>>(gx, Wo, bo, out);
}

// round 11
// speedup vs baseline: 1.7007x; 1.7007x over previous
#include <cuda_runtime.h>
#include <math.h>
#include <stdint.h>

// Problem constants
#define QS    512
#define BATCH 8
#define CDIM  1024
#define NHEAD 16
#define HCDIM 64
#define MMEM  1536
#define NTOK  (QS * BATCH)   // 4096

// Scratch (device globals: allocation-guard safe)
__device__ float g_q[NTOK * CDIM];
__device__ float g_k[NTOK * CDIM];
__device__ float g_v[NTOK * CDIM];
__device__ float g_x[NTOK * CDIM];

__device__ __forceinline__ uint32_t f2tf32(float f) {
    uint32_t u;
    asm("cvt.rna.tf32.f32 %0, %1;" : "=r"(u) : "f"(f));
    return u;
}

__device__ __forceinline__ void mma_tf32(float c[4],
    uint32_t a0, uint32_t a1, uint32_t a2, uint32_t a3,
    uint32_t b0, uint32_t b1)
{
    asm volatile(
        "mma.sync.aligned.m16n8k8.row.col.f32.tf32.tf32.f32 "
        "{%0,%1,%2,%3}, {%4,%5,%6,%7}, {%8,%9}, {%0,%1,%2,%3};"
        : "+f"(c[0]), "+f"(c[1]), "+f"(c[2]), "+f"(c[3])
        : "r"(a0), "r"(a1), "r"(a2), "r"(a3), "r"(b0), "r"(b1));
}

__device__ __forceinline__ void cp16(uint32_t dst, const void* src, int sz) {
    asm volatile("cp.async.cg.shared.global [%0], [%1], 16, %2;"
                 :: "r"(dst), "l"(src), "r"(sz));
}
__device__ __forceinline__ void cp_commit() {
    asm volatile("cp.async.commit_group;");
}
__device__ __forceinline__ void cp_wait0() {
    asm volatile("cp.async.wait_group 0;");
}
__device__ __forceinline__ void cp_wait1() {
    asm volatile("cp.async.wait_group 1;");
}

// ---------------------------------------------------------------------------
// TF32 tensor-core GEMM: out[n][o] = sum_k A[n][k] * W[o][k] + bias[o]
// Block tile 128x128, k-chunk 32, 8 warps (2x4), warp tile 64x32.
// ROUND_OUT: store rna-tf32-rounded values (for q/k/v so the attention
// kernel's truncating consumption sees exact rna values at zero cost).
// The final output projection uses ROUND_OUT=false (full fp32 store).
// ---------------------------------------------------------------------------
template <bool ROUND_OUT>
__global__ __launch_bounds__(256) void gemm_tf32_nt_bias(
    const float* __restrict__ A, const float* __restrict__ W,
    const float* __restrict__ bias, float* __restrict__ out)
{
    __shared__ uint32_t As[128 * 36];
    __shared__ uint32_t Ws[128 * 36];

    const int tid  = threadIdx.x;
    const int lane = tid & 31;
    const int warp = tid >> 5;
    const int g    = lane >> 2;
    const int tig  = lane & 3;

    const int wm = (warp >> 2) * 64;
    const int wn = (warp & 3) * 32;

    const int n0 = blockIdx.y << 7;
    const int o0 = blockIdx.x << 7;

    const int lrow = tid >> 3;
    const int lcol = (tid & 7) << 2;

    float c[4][4][4];
    #pragma unroll
    for (int mi = 0; mi < 4; mi++)
        #pragma unroll
        for (int ni = 0; ni < 4; ni++)
            #pragma unroll
            for (int r = 0; r < 4; r++) c[mi][ni][r] = 0.0f;

    float4 ra[4], rw[4];
    #pragma unroll
    for (int p = 0; p < 4; p++) {
        int r = lrow + (p << 5);
        ra[p] = *(const float4*)(A + (size_t)(n0 + r) * CDIM + lcol);
        rw[p] = *(const float4*)(W + (size_t)(o0 + r) * CDIM + lcol);
    }

    for (int k0 = 0; k0 < CDIM; k0 += 32) {
        #pragma unroll
        for (int p = 0; p < 4; p++) {
            int r = lrow + (p << 5);
            As[r * 36 + lcol + 0] = f2tf32(ra[p].x);
            As[r * 36 + lcol + 1] = f2tf32(ra[p].y);
            As[r * 36 + lcol + 2] = f2tf32(ra[p].z);
            As[r * 36 + lcol + 3] = f2tf32(ra[p].w);
            Ws[r * 36 + lcol + 0] = f2tf32(rw[p].x);
            Ws[r * 36 + lcol + 1] = f2tf32(rw[p].y);
            Ws[r * 36 + lcol + 2] = f2tf32(rw[p].z);
            Ws[r * 36 + lcol + 3] = f2tf32(rw[p].w);
        }
        __syncthreads();

        if (k0 + 32 < CDIM) {
            #pragma unroll
            for (int p = 0; p < 4; p++) {
                int r = lrow + (p << 5);
                ra[p] = *(const float4*)(A + (size_t)(n0 + r) * CDIM + k0 + 32 + lcol);
                rw[p] = *(const float4*)(W + (size_t)(o0 + r) * CDIM + k0 + 32 + lcol);
            }
        }

        #pragma unroll
        for (int ks = 0; ks < 4; ks++) {
            const int kk = ks << 3;
            uint32_t a[4][4], b[4][2];
            #pragma unroll
            for (int mi = 0; mi < 4; mi++) {
                const uint32_t* ap = As + (wm + (mi << 4) + g) * 36 + kk + tig;
                a[mi][0] = ap[0];
                a[mi][1] = ap[8 * 36];
                a[mi][2] = ap[4];
                a[mi][3] = ap[8 * 36 + 4];
            }
            #pragma unroll
            for (int ni = 0; ni < 4; ni++) {
                const uint32_t* bp = Ws + (wn + (ni << 3) + g) * 36 + kk + tig;
                b[ni][0] = bp[0];
                b[ni][1] = bp[4];
            }
            #pragma unroll
            for (int mi = 0; mi < 4; mi++)
                #pragma unroll
                for (int ni = 0; ni < 4; ni++)
                    mma_tf32(c[mi][ni], a[mi][0], a[mi][1], a[mi][2], a[mi][3],
                             b[ni][0], b[ni][1]);
        }
        __syncthreads();
    }

    #pragma unroll
    for (int mi = 0; mi < 4; mi++) {
        int row = n0 + wm + (mi << 4) + g;
        #pragma unroll
        for (int ni = 0; ni < 4; ni++) {
            int col = o0 + wn + (ni << 3) + (tig << 1);
            float b0 = bias[col], b1 = bias[col + 1];
            float r00 = c[mi][ni][0] + b0, r01 = c[mi][ni][1] + b1;
            float r10 = c[mi][ni][2] + b0, r11 = c[mi][ni][3] + b1;
            float2 v0, v1;
            if (ROUND_OUT) {
                v0 = make_float2(__uint_as_float(f2tf32(r00)), __uint_as_float(f2tf32(r01)));
                v1 = make_float2(__uint_as_float(f2tf32(r10)), __uint_as_float(f2tf32(r11)));
            } else {
                v0 = make_float2(r00, r01);
                v1 = make_float2(r10, r11);
            }
            *(float2*)(out + (size_t)row * CDIM + col) = v0;
            *(float2*)(out + (size_t)(row + 8) * CDIM + col) = v1;
        }
    }
}

// ---------------------------------------------------------------------------
// TF32 tensor-core flash attention, 2-stage cp.async pipelined KV gather.
// Grid: (QS/64, BATCH*NHEAD). Block: 128 threads (4 warps), 64q x 64k tiles.
// K stored [kj][d] stride 68, V stored [t][c] stride 72 -- conflict-free.
// Smem operands consumed as raw bits: new-region k/v are pre-rounded (rna)
// by the GEMM epilogue; memkv region is truncated (cheap, slightly noisier).
// NO in-loop conversion (measured: the convert loop cost ~145us in R10).
// ---------------------------------------------------------------------------
#define KSTR 68
#define VSTR 72
#define KV_WORDS (64 * KSTR + 64 * VSTR)   // one stage: 8960 words

__global__ __launch_bounds__(128) void attn_tc_kernel(
    const float* __restrict__ qg, const float* __restrict__ kg,
    const float* __restrict__ vg, const float* __restrict__ memkv,
    const int* __restrict__ memlen, const int* __restrict__ padv,
    const unsigned char* __restrict__ mask, float* __restrict__ xout)
{
    extern __shared__ uint32_t smu[];   // 2 * KV_WORDS = 17920 words = 71680 B
    const uint32_t smem_base = (uint32_t)__cvta_generic_to_shared(smu);

    const int tid  = threadIdx.x;
    const int lane = tid & 31;
    const int warp = tid >> 5;       // 0..3
    const int g    = lane >> 2;      // 0..7
    const int tig  = lane & 3;       // 0..3

    const int s0 = blockIdx.x << 6;
    const int b  = blockIdx.y >> 4;
    const int h  = blockIdx.y & 15;
    const int L  = memlen[b];
    const int P  = padv[b];
    const int Teff = L + P;
    const int qrow0 = warp * 16 + g;

    // ---- Stage Q through smem (buffer 0), then into register fragments ----
    {
        float* Qst = (float*)smu;   // [qi][d] stride 68
        for (int i = tid; i < 1024; i += 128) {
            int qi = i >> 4;
            int dc = (i & 15) << 2;
            float4 qv = *(const float4*)(qg + ((size_t)(s0 + qi) * BATCH + b) * CDIM + h * HCDIM + dc);
            *(float4*)(Qst + qi * KSTR + dc) = qv;
        }
    }
    __syncthreads();

    uint32_t qf[8][4];
    {
        const float* q0 = (const float*)smu + qrow0 * KSTR;
        const float* q8 = q0 + 8 * KSTR;
        #pragma unroll
        for (int ks = 0; ks < 8; ks++) {
            const int kk = ks << 3;
            qf[ks][0] = f2tf32(q0[kk + tig] * 0.125f);
            qf[ks][1] = f2tf32(q8[kk + tig] * 0.125f);
            qf[ks][2] = f2tf32(q0[kk + tig + 4] * 0.125f);
            qf[ks][3] = f2tf32(q8[kk + tig + 4] * 0.125f);
        }
    }
    __syncthreads();  // Q staging consumed before prefetch overwrites buffer 0

    float oacc[8][4];
    #pragma unroll
    for (int ni = 0; ni < 8; ni++)
        #pragma unroll
        for (int r = 0; r < 4; r++) oacc[ni][r] = 0.0f;
    float mrow[2] = { -INFINITY, -INFINITY };
    float lrow[2] = { 0.0f, 0.0f };

    const int ntile = (Teff + 63) >> 6;

    // ---- KV gather into stage buffer via cp.async ----
    auto gather = [&](int kt) {
        const int t0 = kt << 6;
        const uint32_t kbase = smem_base + (uint32_t)((kt & 1) * KV_WORDS) * 4u;
        const uint32_t vbase = kbase + 64 * KSTR * 4u;
        for (int i = tid; i < 1024; i += 128) {
            int kj = i >> 4;
            int dc = (i & 15) << 2;
            int t = t0 + kj;
            const float* srcK = kg;
            const float* srcV = vg;
            int sz = 0;
            if (t < L) {
                const float* bp = memkv + (((size_t)t * BATCH + b) * NHEAD + h) * (2 * HCDIM);
                srcK = bp + dc;
                srcV = bp + HCDIM + dc;
                sz = 16;
            } else if (t < Teff) {
                int j = t - L;
                srcK = kg + ((size_t)j * BATCH + b) * CDIM + h * HCDIM + dc;
                srcV = vg + ((size_t)j * BATCH + b) * CDIM + h * HCDIM + dc;
                sz = 16;
            }
            cp16(kbase + (uint32_t)(kj * KSTR + dc) * 4u, srcK, sz);
            cp16(vbase + (uint32_t)(kj * VSTR + dc) * 4u, srcV, sz);
        }
        cp_commit();
    };

    if (ntile > 0) gather(0);

    for (int kt = 0; kt < ntile; kt++) {
        const int t0 = kt << 6;
        if (kt + 1 < ntile) { gather(kt + 1); cp_wait1(); }
        else                { cp_wait0(); }
        __syncthreads();

        const uint32_t* Kb = smu + (kt & 1) * KV_WORDS;
        const uint32_t* Vb = Kb + 64 * KSTR;

        // S = Q K^T
        float sv[8][4];
        #pragma unroll
        for (int ni = 0; ni < 8; ni++)
            #pragma unroll
            for (int r = 0; r < 4; r++) sv[ni][r] = 0.0f;

        #pragma unroll
        for (int ks = 0; ks < 8; ks++) {
            const int kk = ks << 3;
            #pragma unroll
            for (int ni = 0; ni < 8; ni++) {
                const uint32_t* bp = Kb + ((ni << 3) + g) * KSTR + kk + tig;
                mma_tf32(sv[ni], qf[ks][0], qf[ks][1], qf[ks][2], qf[ks][3],
                         bp[0], bp[4]);
            }
        }

        // Masking -- skipped entirely for tiles fully inside memory region
        if (t0 + 64 > L) {
            #pragma unroll
            for (int ni = 0; ni < 8; ni++) {
                #pragma unroll
                for (int cc = 0; cc < 2; cc++) {
                    int t = t0 + (ni << 3) + (tig << 1) + cc;
                    if (t >= Teff) {
                        sv[ni][cc] = -INFINITY;
                        sv[ni][2 + cc] = -INFINITY;
                    } else if (t >= L) {
                        int jn = t - L;
                        int r0 = s0 + qrow0;
                        if (mask[((size_t)r0 * QS + jn) * BATCH + b]) sv[ni][cc] = -INFINITY;
                        if (mask[((size_t)(r0 + 8) * QS + jn) * BATCH + b]) sv[ni][2 + cc] = -INFINITY;
                    }
                }
            }
        }

        // Online softmax per row-half (row spread over 4 tig lanes)
        #pragma unroll
        for (int half = 0; half < 2; half++) {
            const int o0i = half << 1;
            float rm = -INFINITY;
            #pragma unroll
            for (int ni = 0; ni < 8; ni++)
                rm = fmaxf(rm, fmaxf(sv[ni][o0i], sv[ni][o0i + 1]));
            rm = fmaxf(rm, __shfl_xor_sync(0xffffffffu, rm, 1));
            rm = fmaxf(rm, __shfl_xor_sync(0xffffffffu, rm, 2));
            float mn = fmaxf(mrow[half], rm);
            float factor = (mn == -INFINITY) ? 1.0f : __expf(mrow[half] - mn);
            float rs = 0.0f;
            #pragma unroll
            for (int ni = 0; ni < 8; ni++) {
                #pragma unroll
                for (int cc = 0; cc < 2; cc++) {
                    float p = (mn == -INFINITY) ? 0.0f : __expf(sv[ni][o0i + cc] - mn);
                    sv[ni][o0i + cc] = p;
                    rs += p;
                }
            }
            rs += __shfl_xor_sync(0xffffffffu, rs, 1);
            rs += __shfl_xor_sync(0xffffffffu, rs, 2);
            lrow[half] = lrow[half] * factor + rs;
            mrow[half] = mn;
            #pragma unroll
            for (int ni = 0; ni < 8; ni++) {
                oacc[ni][o0i] *= factor;
                oacc[ni][o0i + 1] *= factor;
            }
        }

        // O += P V. P C-frag -> A-frag via intra-group shuffles:
        // col c of block ks lives at lane (g*4 + (c>>1)), slot (c&1).
        const int srcA = (lane & ~3) + (tig >> 1);
        const int srcB = srcA + 2;
        const int sel  = tig & 1;
        #pragma unroll
        for (int ks = 0; ks < 8; ks++) {
            float s0a = __shfl_sync(0xffffffffu, sv[ks][0], srcA);
            float s1a = __shfl_sync(0xffffffffu, sv[ks][1], srcA);
            float s2a = __shfl_sync(0xffffffffu, sv[ks][2], srcA);
            float s3a = __shfl_sync(0xffffffffu, sv[ks][3], srcA);
            float s0b = __shfl_sync(0xffffffffu, sv[ks][0], srcB);
            float s1b = __shfl_sync(0xffffffffu, sv[ks][1], srcB);
            float s2b = __shfl_sync(0xffffffffu, sv[ks][2], srcB);
            float s3b = __shfl_sync(0xffffffffu, sv[ks][3], srcB);
            uint32_t pa0 = f2tf32(sel ? s1a : s0a);   // P[g][8ks+tig]
            uint32_t pa1 = f2tf32(sel ? s3a : s2a);   // P[g+8][8ks+tig]
            uint32_t pa2 = f2tf32(sel ? s1b : s0b);   // P[g][8ks+tig+4]
            uint32_t pa3 = f2tf32(sel ? s3b : s2b);   // P[g+8][8ks+tig+4]

            const int kk = ks << 3;
            #pragma unroll
            for (int ni = 0; ni < 8; ni++) {
                const uint32_t* bp = Vb + (kk + tig) * VSTR + (ni << 3) + g;
                mma_tf32(oacc[ni], pa0, pa1, pa2, pa3, bp[0], bp[4 * VSTR]);
            }
        }
        __syncthreads();  // done reading this stage before it becomes prefetch target
    }

    // Normalize and write x[s][b][c] (all-masked rows -> 0)
    #pragma unroll
    for (int half = 0; half < 2; half++) {
        float inv = (lrow[half] > 0.0f) ? 1.0f / lrow[half] : 0.0f;
        int row = s0 + qrow0 + (half << 3);
        float* orow = xout + ((size_t)row * BATCH + b) * CDIM + h * HCDIM;
        #pragma unroll
        for (int ni = 0; ni < 8; ni++) {
            int col = (ni << 3) + (tig << 1);
            float2 v = make_float2(oacc[ni][(half << 1)] * inv,
                                   oacc[ni][(half << 1) + 1] * inv);
            *(float2*)(orow + col) = v;
        }
    }
}

// ---------------------------------------------------------------------------
// Launch
// ---------------------------------------------------------------------------
extern "C" void kernel_launch(void* const* d_in, const int* in_sizes, int n_in,
                              void* d_out, int out_size)
{
    const float*         xq     = (const float*)d_in[0];
    const int*           pad    = (const int*)d_in[1];
    const unsigned char* mask   = (const unsigned char*)d_in[2];
    const int*           memlen = (const int*)d_in[3];
    const float*         memkv  = (const float*)d_in[4];
    const float* Wq = (const float*)d_in[5];  const float* bq = (const float*)d_in[6];
    const float* Wk = (const float*)d_in[7];  const float* bk = (const float*)d_in[8];
    const float* Wv = (const float*)d_in[9];  const float* bv = (const float*)d_in[10];
    const float* Wo = (const float*)d_in[11]; const float* bo = (const float*)d_in[12];
    float* out = (float*)d_out;

    float *gq, *gk, *gv, *gx;
    cudaGetSymbolAddress((void**)&gq, g_q);
    cudaGetSymbolAddress((void**)&gk, g_k);
    cudaGetSymbolAddress((void**)&gv, g_v);
    cudaGetSymbolAddress((void**)&gx, g_x);

    dim3 gg(CDIM / 128, NTOK / 128);  // (8, 32)
    // q/k/v projections: store rna-rounded (free precision for attention)
    gemm_tf32_nt_bias<true><<<gg, 256>>>(xq, Wq, bq, gq);
    gemm_tf32_nt_bias<true><<<gg, 256>>>(xq, Wk, bk, gk);
    gemm_tf32_nt_bias<true><<<gg, 256>>>(xq, Wv, bv, gv);

    const int smem_bytes = 2 * KV_WORDS * (int)sizeof(uint32_t);  // 71680
    cudaFuncSetAttribute(attn_tc_kernel, cudaFuncAttributeMaxDynamicSharedMemorySize, smem_bytes);
    attn_tc_kernel<<<dim3(QS / 64, BATCH * NHEAD), 128, smem_bytes>>>(
        gq, gk, gv, memkv, memlen, pad, mask, gx);

    // Output projection: full fp32 store
    gemm_tf32_nt_bias<false><<<gg, 256>>>(gx, Wo, bo, out);
}